// round 17
// baseline (speedup 1.0000x reference)
#include <cuda_runtime.h>
#include <math.h>

#define TSTEPS  2048
#define FDIM    15
#define NGROUPS 8
#define BG      8
#define NT      384
#define NCTA    128
#define SPH     260
#define WS      260
#define RB1     52
#define RKC1    420    // 8*RB1 + 4
#define RB2     100
#define RKC2    804    // 8*RB2 + 4

typedef unsigned long long u64;

// 4-deep buffered hidden states (live in L2)
__device__ float    g_h1[4 * NGROUPS * BG * 256];
__device__ float    g_h2[4 * NGROUPS * BG * 256];
__device__ unsigned g_f1[NCTA];
__device__ unsigned g_f2[NCTA];

__global__ void init_kernel() {
    if (threadIdx.x < NCTA) {
        g_f1[threadIdx.x] = 0u;
        g_f2[threadIdx.x] = 0u;
    }
}

__device__ __forceinline__ float sigmoidf_(float x) {
    return __fdividef(1.0f, 1.0f + __expf(-x));
}

__device__ __forceinline__ u64 ffma2(u64 a, u64 b, u64 c) {
    u64 d;
    asm("fma.rn.f32x2 %0, %1, %2, %3;" : "=l"(d) : "l"(a), "l"(b), "l"(c));
    return d;
}

// engine-internal named barrier (192 threads)
__device__ __forceinline__ void nbar(int id) {
    asm volatile("bar.sync %0, 192;" :: "r"(id) : "memory");
}

// one warp polls both flag arrays of its group: lanes 0-15 -> f1 >= t1, 16-31 -> f2 >= t2
__device__ __forceinline__ void poll2(int grp, unsigned t1, unsigned t2) {
    int lane = threadIdx.x & 31;
    const volatile unsigned* a = (lane < 16)
        ? ((volatile unsigned*)g_f1) + grp * 16 + lane
        : ((volatile unsigned*)g_f2) + grp * 16 + (lane - 16);
    unsigned t = (lane < 16) ? t1 : t2;
    for (;;) {
        if (__all_sync(0xffffffffu, *a >= t)) break;
    }
    if (lane == 0) __threadfence();
}

__global__ void __launch_bounds__(NT, 1)
gru_kernel(const float* __restrict__ inp, const float* __restrict__ W1,
           const float* __restrict__ U1g, const float* __restrict__ b1,
           const float* __restrict__ W2g, const float* __restrict__ U2g,
           const float* __restrict__ b2, float* __restrict__ out)
{
    extern __shared__ float smem[];
    float* sW   = smem;                 // [144][WS]: 0..47 U1, 48..95 W2, 96..143 U2 (transposed)
    float* sh1a = sW   + 144 * WS;      // [8][SPH]  L1 engine: h1[i-1]
    float* sh1b = sh1a +   8 * SPH;     // [8][SPH]  L2 engine: h1[j]
    float* sh2  = sh1b +   8 * SPH;     // [8][SPH]  L2 engine: h2[j-1]
    float* sW1t = sh2  +   8 * SPH;     // [48][16]
    float* sx   = sW1t +  48 * 16;      // [8][16]
    float* sb   = sx   +   8 * 16;      // [4*48]: b1_in | b1_rec | b2_in | b2_rec
    float* red1 = sb   +   4 * 48;      // [8 kc][8 rows * RB1]
    float* red2 = red1 +   8 * RKC1;    // [8 kc][8 rows * RB2]

    const int tid   = threadIdx.x;
    const int cta   = blockIdx.x;
    const int grp   = cta >> 4;
    const int sl    = cta & 15;
    const int brow0 = grp * BG;

    // ---- one-time init ----
    for (int idx = tid; idx < 48 * 256; idx += NT) {
        int k = idx / 48, c = idx - k * 48;
        int col = ((c >> 4) << 8) + (sl << 4) + (c & 15);
        sW[c * WS + k]          = U1g[k * 768 + col];
        sW[(48 + c) * WS + k]   = W2g[k * 768 + col];
        sW[(96 + c) * WS + k]   = U2g[k * 768 + col];
    }
    for (int idx = tid; idx < 48 * 15; idx += NT) {
        int f = idx / 48, c = idx - f * 48;
        int col = ((c >> 4) << 8) + (sl << 4) + (c & 15);
        sW1t[c * 16 + f] = W1[f * 768 + col];
    }
    for (int c = tid; c < 48; c += NT) {
        int col = ((c >> 4) << 8) + (sl << 4) + (c & 15);
        sb[c]        = b1[col];
        sb[48 + c]   = b1[768 + col];
        sb[96 + c]   = b2[col];
        sb[144 + c]  = b2[768 + col];
    }
    if (tid < 128) {
        int b = tid & 7, u = tid >> 3;
        int scol = (sl << 4) + u;
        for (int buf = 0; buf < 4; buf++) {
            g_h1[(buf * NGROUPS + grp) * BG * 256 + b * 256 + scol] = 0.f;
            g_h2[(buf * NGROUPS + grp) * BG * 256 + b * 256 + scol] = 0.f;
        }
    }
    __syncthreads();
    if (tid == 0) {
        __threadfence();
        atomicExch(&g_f1[cta], 1u);   // h1[-1] (zeros) ready
        atomicExch(&g_f2[cta], 1u);   // h2[-1] (zeros) ready
    }

    const int wid = tid >> 5;

    if (wid < 6) {
        // ================= L1 ENGINE (warps 0-5): critical path =================
        const int e   = tid;                 // 0..191
        const int kc  = e / 24;              // 0..7
        const int r24 = e - kc * 24;
        const int cg  = r24 >> 1;            // 0..11 (cols cg*4..cg*4+3 of U1)
        const int rh  = r24 & 1;             // rows rh*4..rh*4+3
        const float* hsel = sh1a + rh * 4 * SPH + kc * 32;
        const float* wbse = sW + (cg * 4) * WS + kc * 32;
        const int b15 = e / 15, f15 = e - b15 * 15;
        float hp1 = 0.f;                     // own state (e < 128)

        for (int i = 0; i < TSTEPS; ++i) {
            float xin = 0.f;
            if (e < 120)
                xin = __ldg(&inp[(size_t)(brow0 + b15) * (TSTEPS * FDIM) + i * FDIM + f15]);

            if (wid == 0)
                poll2(grp, (unsigned)(i + 1), (i >= 4) ? (unsigned)(i - 2) : 0u);
            nbar(1);

            // load h1[i-1] from buffer (i+3)&3
            {
                const float* gh1 = g_h1 + (((i + 3) & 3) * NGROUPS + grp) * BG * 256;
                for (int idx = e; idx < 512; idx += 192) {
                    int b = idx >> 6, k4 = idx & 63;
                    float4 v = __ldcg(((const float4*)(gh1 + b * 256)) + k4);
                    *(float4*)(sh1a + b * SPH + (k4 << 2)) = v;
                }
                if (e < 120) sx[b15 * 16 + f15] = xin;
            }
            nbar(1);

            // GEMM rec1 = h1[i-1] @ U1 slice (8 x 48 x 256)
            {
                u64 acc[4][4];
                #pragma unroll
                for (int j = 0; j < 4; j++)
                    #pragma unroll
                    for (int jj = 0; jj < 4; jj++) acc[j][jj] = 0ull;
                #pragma unroll
                for (int s = 0; s < 8; s++) {
                    ulonglong2 hv[4];
                    #pragma unroll
                    for (int j = 0; j < 4; j++)
                        hv[j] = *(const ulonglong2*)(hsel + j * SPH + s * 4);
                    #pragma unroll
                    for (int jj = 0; jj < 4; jj++) {
                        ulonglong2 w2 = *(const ulonglong2*)(wbse + jj * WS + s * 4);
                        #pragma unroll
                        for (int j = 0; j < 4; j++) {
                            acc[j][jj] = ffma2(hv[j].x, w2.x, acc[j][jj]);
                            acc[j][jj] = ffma2(hv[j].y, w2.y, acc[j][jj]);
                        }
                    }
                }
                #pragma unroll
                for (int j = 0; j < 4; j++) {
                    int row = rh * 4 + j;
                    #pragma unroll
                    for (int jj = 0; jj < 4; jj += 2) {
                        float2 p0 = *(float2*)&acc[j][jj];
                        float2 p1 = *(float2*)&acc[j][jj + 1];
                        *(float2*)&red1[kc * RKC1 + row * RB1 + cg * 4 + jj] =
                            make_float2(p0.x + p0.y, p1.x + p1.y);
                    }
                }
            }
            nbar(1);

            // gates: h1[i]
            if (e < 128) {
                int b = e & 7, u = e >> 3;
                int scol = (sl << 4) + u;
                const float* rrow = red1 + b * RB1;
                float rec[3], xp[3];
                #pragma unroll
                for (int g = 0; g < 3; g++) {
                    int c = g * 16 + u;
                    float s = rrow[c];
                    #pragma unroll
                    for (int k2 = 1; k2 < 8; k2++) s += rrow[k2 * RKC1 + c];
                    rec[g] = s + sb[48 + c];
                    float a = sb[c];
                    const float* wr = sW1t + c * 16;
                    const float* xr = sx + b * 16;
                    #pragma unroll
                    for (int f = 0; f < 15; f++) a += xr[f] * wr[f];
                    xp[g] = a;
                }
                float z  = sigmoidf_(xp[0] + rec[0]);
                float r  = sigmoidf_(xp[1] + rec[1]);
                float hh = fmaxf(0.f, xp[2] + r * rec[2]);
                float hn = z * hp1 + (1.f - z) * hh;
                hp1 = hn;
                g_h1[((i & 3) * NGROUPS + grp) * BG * 256 + b * 256 + scol] = hn;
                if (i == TSTEPS - 1) out[64 * 256 + (brow0 + b) * 256 + scol] = hn;  // state1
            }
            nbar(1);
            if (e == 0) {
                __threadfence();
                atomicExch(&g_f1[cta], (unsigned)(i + 2));
            }
        }
    } else {
        // ================= L2 ENGINE (warps 6-11): trailing pipeline =================
        const int e   = tid - 192;           // 0..191
        const int kc  = e / 24;              // 0..7
        const int r24 = e - kc * 24;
        const int cg  = r24 >> 1;            // 0..11 (cols cg*8..cg*8+7; cg<6 -> W2/h1, else U2/h2)
        const int rh  = r24 & 1;
        const float* hsel = (cg < 6 ? sh1b : sh2) + rh * 4 * SPH + kc * 32;
        const float* wbse = sW + (48 + cg * 8) * WS + kc * 32;
        float hp2 = 0.f;                     // own state (e < 128)

        for (int j = 0; j < TSTEPS; ++j) {
            if (wid == 6)
                poll2(grp, (unsigned)(j + 2), (unsigned)(j + 1));
            nbar(2);

            // load h1[j] (buffer j&3) and h2[j-1] (buffer (j+3)&3)
            {
                const float* gh1 = g_h1 + (((j) & 3)     * NGROUPS + grp) * BG * 256;
                const float* gh2 = g_h2 + (((j + 3) & 3) * NGROUPS + grp) * BG * 256;
                for (int idx = e; idx < 512; idx += 192) {
                    int b = idx >> 6, k4 = idx & 63;
                    float4 v1 = __ldcg(((const float4*)(gh1 + b * 256)) + k4);
                    float4 v2 = __ldcg(((const float4*)(gh2 + b * 256)) + k4);
                    *(float4*)(sh1b + b * SPH + (k4 << 2)) = v1;
                    *(float4*)(sh2  + b * SPH + (k4 << 2)) = v2;
                }
            }
            nbar(2);

            // GEMM [xp2 | rec2] = [h1[j] @ W2 | h2[j-1] @ U2]  (8 x 96 x 256)
            {
                u64 acc[4][8];
                #pragma unroll
                for (int jr = 0; jr < 4; jr++)
                    #pragma unroll
                    for (int jj = 0; jj < 8; jj++) acc[jr][jj] = 0ull;
                #pragma unroll
                for (int s = 0; s < 8; s++) {
                    ulonglong2 hv[4];
                    #pragma unroll
                    for (int jr = 0; jr < 4; jr++)
                        hv[jr] = *(const ulonglong2*)(hsel + jr * SPH + s * 4);
                    #pragma unroll
                    for (int jj = 0; jj < 8; jj++) {
                        ulonglong2 w2 = *(const ulonglong2*)(wbse + jj * WS + s * 4);
                        #pragma unroll
                        for (int jr = 0; jr < 4; jr++) {
                            acc[jr][jj] = ffma2(hv[jr].x, w2.x, acc[jr][jj]);
                            acc[jr][jj] = ffma2(hv[jr].y, w2.y, acc[jr][jj]);
                        }
                    }
                }
                #pragma unroll
                for (int jr = 0; jr < 4; jr++) {
                    int row = rh * 4 + jr;
                    #pragma unroll
                    for (int jj = 0; jj < 8; jj += 2) {
                        float2 p0 = *(float2*)&acc[jr][jj];
                        float2 p1 = *(float2*)&acc[jr][jj + 1];
                        *(float2*)&red2[kc * RKC2 + row * RB2 + cg * 8 + jj] =
                            make_float2(p0.x + p0.y, p1.x + p1.y);
                    }
                }
            }
            nbar(2);

            // gates: h2[j]
            if (e < 128) {
                int b = e & 7, u = e >> 3;
                int scol = (sl << 4) + u;
                int gb = brow0 + b;
                const float* rrow = red2 + b * RB2;
                float xpv[3], rec[3];
                #pragma unroll
                for (int g = 0; g < 3; g++) {
                    int cx = g * 16 + u;          // W2 cols 0..47
                    int cr = 48 + g * 16 + u;     // U2 cols 48..95
                    float sx_ = rrow[cx];
                    float sr_ = rrow[cr];
                    #pragma unroll
                    for (int k2 = 1; k2 < 8; k2++) {
                        sx_ += rrow[k2 * RKC2 + cx];
                        sr_ += rrow[k2 * RKC2 + cr];
                    }
                    xpv[g] = sx_ + sb[96 + g * 16 + u];
                    rec[g] = sr_ + sb[144 + g * 16 + u];
                }
                float z  = sigmoidf_(xpv[0] + rec[0]);
                float r  = sigmoidf_(xpv[1] + rec[1]);
                float hh = fmaxf(0.f, xpv[2] + r * rec[2]);
                float hn = z * hp2 + (1.f - z) * hh;
                hp2 = hn;
                g_h2[((j & 3) * NGROUPS + grp) * BG * 256 + b * 256 + scol] = hn;
                if (j == TSTEPS - 1) {
                    out[gb * 256 + scol]                = hn;   // x = seq2[:, -1, :]
                    out[2 * 64 * 256 + gb * 256 + scol] = hn;   // state2
                }
            }
            nbar(2);
            if (e == 0) {
                __threadfence();
                atomicExch(&g_f2[cta], (unsigned)(j + 2));
            }
        }
    }
}

extern "C" void kernel_launch(void* const* d_in, const int* in_sizes, int n_in,
                              void* d_out, int out_size) {
    const float* inp = (const float*)d_in[0];
    const float* W1  = (const float*)d_in[1];
    const float* U1  = (const float*)d_in[2];
    const float* b1  = (const float*)d_in[3];
    const float* W2  = (const float*)d_in[4];
    const float* U2  = (const float*)d_in[5];
    const float* b2  = (const float*)d_in[6];
    float* out = (float*)d_out;

    size_t smem_bytes = (size_t)(144 * WS + 3 * 8 * SPH +
                                 48 * 16 + 8 * 16 + 4 * 48 +
                                 8 * RKC1 + 8 * RKC2) * sizeof(float);
    cudaFuncSetAttribute(gru_kernel, cudaFuncAttributeMaxDynamicSharedMemorySize,
                         (int)smem_bytes);
    init_kernel<<<1, 128>>>();
    gru_kernel<<<NCTA, NT, smem_bytes>>>(inp, W1, U1, b1, W2, U2, b2, out);
}